// round 1
// baseline (speedup 1.0000x reference)
#include <cuda_runtime.h>
#include <math.h>

// Problem constants
#define B_   2
#define S_   2048
#define H_   16
#define DH_  64
#define D_   1024
#define HID_ 4096
#define M_   (B_*S_)   // 4096 tokens

// ---------------- scratch (static device globals; no runtime alloc) ----------
__device__ float g_q  [(size_t)M_*D_];
__device__ float g_k  [(size_t)M_*D_];
__device__ float g_v  [(size_t)M_*D_];
__device__ float g_ao [(size_t)M_*D_];
__device__ float g_t1 [(size_t)M_*D_];
__device__ float g_h  [(size_t)M_*D_];
__device__ float g_hid[(size_t)M_*HID_];

// ---------------- generic NN SGEMM: C[M,N] = A[M,K] @ B[K,N] + bias ----------
// 128x128 tile, BK=8, 256 threads, 8x8 microtile. M%128==0, N%128==0, K%8==0.
// ACT: 0 = none, 1 = exact gelu
template<int ACT>
__global__ __launch_bounds__(256) void sgemm_nn(
    const float* __restrict__ A, const float* __restrict__ Bm,
    const float* __restrict__ bias, float* __restrict__ C,
    int M, int N, int K)
{
    __shared__ float As[8][128];
    __shared__ float Bs[8][128];
    const int tid = threadIdx.x;
    const int tx = tid & 15;
    const int ty = tid >> 4;
    const int row0 = blockIdx.y * 128;
    const int col0 = blockIdx.x * 128;

    const int a_row = tid >> 1;
    const int a_col = (tid & 1) * 4;
    const int b_row = tid >> 5;
    const int b_col = (tid & 31) * 4;

    const float* Ap = A + (size_t)(row0 + a_row) * K + a_col;
    const float* Bp = Bm + (size_t)b_row * N + col0 + b_col;

    float acc[8][8];
#pragma unroll
    for (int i = 0; i < 8; i++)
#pragma unroll
        for (int j = 0; j < 8; j++) acc[i][j] = 0.f;

    for (int k0 = 0; k0 < K; k0 += 8) {
        float4 av = *(const float4*)(Ap + k0);
        float4 bv = *(const float4*)(Bp + (size_t)k0 * N);
        As[a_col + 0][a_row] = av.x;
        As[a_col + 1][a_row] = av.y;
        As[a_col + 2][a_row] = av.z;
        As[a_col + 3][a_row] = av.w;
        *(float4*)&Bs[b_row][b_col] = bv;
        __syncthreads();
#pragma unroll
        for (int kk = 0; kk < 8; kk++) {
            float a[8], b[8];
#pragma unroll
            for (int i = 0; i < 8; i++) a[i] = As[kk][ty * 8 + i];
#pragma unroll
            for (int j = 0; j < 8; j++) b[j] = Bs[kk][tx * 8 + j];
#pragma unroll
            for (int i = 0; i < 8; i++)
#pragma unroll
                for (int j = 0; j < 8; j++)
                    acc[i][j] = fmaf(a[i], b[j], acc[i][j]);
        }
        __syncthreads();
    }

#pragma unroll
    for (int i = 0; i < 8; i++) {
        float* Cp = C + (size_t)(row0 + ty * 8 + i) * N + col0 + tx * 8;
        float o[8];
#pragma unroll
        for (int j = 0; j < 8; j++) {
            float vv = acc[i][j] + bias[col0 + tx * 8 + j];
            if (ACT == 1) vv = 0.5f * vv * (1.0f + erff(vv * 0.70710678118654752f));
            o[j] = vv;
        }
        *(float4*)(Cp + 0) = make_float4(o[0], o[1], o[2], o[3]);
        *(float4*)(Cp + 4) = make_float4(o[4], o[5], o[6], o[7]);
    }
}

// ---------------- batched NT GEMM: E[bh][s,t] = sum_d q[s,d]*k[t,d] ----------
// q,k layout [B,S,H,DH] -> per (b,h): row stride H_*DH_ = 1024. K = 64.
__global__ __launch_bounds__(256) void energy_kernel(
    const float* __restrict__ q, const float* __restrict__ k,
    float* __restrict__ E)
{
    __shared__ float Qs[8][128];
    __shared__ float Ks[8][128];
    const int tid = threadIdx.x;
    const int tx = tid & 15;
    const int ty = tid >> 4;
    const int bh = blockIdx.z;
    const int b = bh >> 4;
    const int h = bh & 15;
    const int row0 = blockIdx.y * 128;
    const int col0 = blockIdx.x * 128;

    const float* qb = q + ((size_t)b * S_ * H_ + h) * DH_;
    const float* kb = k + ((size_t)b * S_ * H_ + h) * DH_;
    float* Eb = E + (size_t)bh * S_ * S_;

    const int a_row = tid >> 1;
    const int a_col = (tid & 1) * 4;
    const float* qp = qb + (size_t)(row0 + a_row) * (H_ * DH_) + a_col;
    const float* kp = kb + (size_t)(col0 + a_row) * (H_ * DH_) + a_col;

    float acc[8][8];
#pragma unroll
    for (int i = 0; i < 8; i++)
#pragma unroll
        for (int j = 0; j < 8; j++) acc[i][j] = 0.f;

    for (int k0 = 0; k0 < DH_; k0 += 8) {
        float4 av = *(const float4*)(qp + k0);
        float4 bv = *(const float4*)(kp + k0);
        Qs[a_col + 0][a_row] = av.x;
        Qs[a_col + 1][a_row] = av.y;
        Qs[a_col + 2][a_row] = av.z;
        Qs[a_col + 3][a_row] = av.w;
        Ks[a_col + 0][a_row] = bv.x;
        Ks[a_col + 1][a_row] = bv.y;
        Ks[a_col + 2][a_row] = bv.z;
        Ks[a_col + 3][a_row] = bv.w;
        __syncthreads();
#pragma unroll
        for (int kk = 0; kk < 8; kk++) {
            float a[8], bb[8];
#pragma unroll
            for (int i = 0; i < 8; i++) a[i] = Qs[kk][ty * 8 + i];
#pragma unroll
            for (int j = 0; j < 8; j++) bb[j] = Ks[kk][tx * 8 + j];
#pragma unroll
            for (int i = 0; i < 8; i++)
#pragma unroll
                for (int j = 0; j < 8; j++)
                    acc[i][j] = fmaf(a[i], bb[j], acc[i][j]);
        }
        __syncthreads();
    }

#pragma unroll
    for (int i = 0; i < 8; i++) {
        float* Ep = Eb + (size_t)(row0 + ty * 8 + i) * S_ + col0 + tx * 8;
        *(float4*)(Ep + 0) = make_float4(acc[i][0], acc[i][1], acc[i][2], acc[i][3]);
        *(float4*)(Ep + 4) = make_float4(acc[i][4], acc[i][5], acc[i][6], acc[i][7]);
    }
}

// ---------------- in-place softmax over rows of length S_, scale 1/8 --------
__global__ __launch_bounds__(256) void softmax_kernel(float* __restrict__ P)
{
    const size_t row = blockIdx.x;
    float* p = P + row * (size_t)S_;
    const int tid = threadIdx.x;

    float v[8];
    float4 v0 = *(const float4*)(p + tid * 8);
    float4 v1 = *(const float4*)(p + tid * 8 + 4);
    v[0] = v0.x; v[1] = v0.y; v[2] = v0.z; v[3] = v0.w;
    v[4] = v1.x; v[5] = v1.y; v[6] = v1.z; v[7] = v1.w;

    float m = v[0];
#pragma unroll
    for (int i = 1; i < 8; i++) m = fmaxf(m, v[i]);
#pragma unroll
    for (int o = 16; o; o >>= 1) m = fmaxf(m, __shfl_xor_sync(0xffffffffu, m, o));

    __shared__ float rmax[8];
    __shared__ float rsum[8];
    if ((tid & 31) == 0) rmax[tid >> 5] = m;
    __syncthreads();
    m = rmax[0];
#pragma unroll
    for (int w = 1; w < 8; w++) m = fmaxf(m, rmax[w]);

    float s = 0.f;
#pragma unroll
    for (int i = 0; i < 8; i++) {
        v[i] = expf((v[i] - m) * 0.125f);
        s += v[i];
    }
#pragma unroll
    for (int o = 16; o; o >>= 1) s += __shfl_xor_sync(0xffffffffu, s, o);
    if ((tid & 31) == 0) rsum[tid >> 5] = s;
    __syncthreads();
    s = 0.f;
#pragma unroll
    for (int w = 0; w < 8; w++) s += rsum[w];
    float inv = 1.0f / s;

    *(float4*)(p + tid * 8)     = make_float4(v[0]*inv, v[1]*inv, v[2]*inv, v[3]*inv);
    *(float4*)(p + tid * 8 + 4) = make_float4(v[4]*inv, v[5]*inv, v[6]*inv, v[7]*inv);
}

// ---------------- batched NN: O[s,d] = sum_t P[s,t] * v[t,d], N = 64 --------
// P row stride S_; v per-head row stride 1024; O into [B,S,H,DH].
__global__ __launch_bounds__(256) void av_kernel(
    const float* __restrict__ P, const float* __restrict__ v,
    float* __restrict__ O)
{
    __shared__ float Ps[16][128];
    __shared__ float Vs[16][64];
    const int tid = threadIdx.x;
    const int tx = tid & 15;     // 16 x 4 = 64 cols
    const int ty = tid >> 4;     // 16 x 8 = 128 rows
    const int bh = blockIdx.z;
    const int b = bh >> 4;
    const int h = bh & 15;
    const int row0 = blockIdx.y * 128;

    const float* Pb = P + (size_t)bh * S_ * S_;
    const float* vb = v + ((size_t)b * S_ * H_ + h) * DH_;
    float* Ob = O + ((size_t)b * S_ * H_ + h) * DH_;

    const int p_r = tid >> 2;          // 0..63
    const int p_c = (tid & 3) * 4;     // 0,4,8,12
    const int v_r = tid >> 4;          // 0..15
    const int v_c = (tid & 15) * 4;    // 0..60

    float acc[8][4];
#pragma unroll
    for (int i = 0; i < 8; i++)
#pragma unroll
        for (int j = 0; j < 4; j++) acc[i][j] = 0.f;

    for (int k0 = 0; k0 < S_; k0 += 16) {
        float4 p0 = *(const float4*)(Pb + (size_t)(row0 + p_r) * S_ + k0 + p_c);
        float4 p1 = *(const float4*)(Pb + (size_t)(row0 + p_r + 64) * S_ + k0 + p_c);
        float4 vv = *(const float4*)(vb + (size_t)(k0 + v_r) * (H_ * DH_) + v_c);
        Ps[p_c + 0][p_r] = p0.x;
        Ps[p_c + 1][p_r] = p0.y;
        Ps[p_c + 2][p_r] = p0.z;
        Ps[p_c + 3][p_r] = p0.w;
        Ps[p_c + 0][p_r + 64] = p1.x;
        Ps[p_c + 1][p_r + 64] = p1.y;
        Ps[p_c + 2][p_r + 64] = p1.z;
        Ps[p_c + 3][p_r + 64] = p1.w;
        *(float4*)&Vs[v_r][v_c] = vv;
        __syncthreads();
#pragma unroll
        for (int kk = 0; kk < 16; kk++) {
            float a[8], bb[4];
#pragma unroll
            for (int i = 0; i < 8; i++) a[i] = Ps[kk][ty * 8 + i];
#pragma unroll
            for (int j = 0; j < 4; j++) bb[j] = Vs[kk][tx * 4 + j];
#pragma unroll
            for (int i = 0; i < 8; i++)
#pragma unroll
                for (int j = 0; j < 4; j++)
                    acc[i][j] = fmaf(a[i], bb[j], acc[i][j]);
        }
        __syncthreads();
    }

#pragma unroll
    for (int i = 0; i < 8; i++) {
        float* Op = Ob + (size_t)(row0 + ty * 8 + i) * (H_ * DH_) + tx * 4;
        *(float4*)Op = make_float4(acc[i][0], acc[i][1], acc[i][2], acc[i][3]);
    }
}

// ---------------- fused residual add + LayerNorm over D_ = 1024 -------------
__global__ __launch_bounds__(256) void add_ln_kernel(
    const float* __restrict__ a, const float* __restrict__ bres,
    const float* __restrict__ gamma, const float* __restrict__ beta,
    float* __restrict__ out)
{
    const size_t row = blockIdx.x;
    const int tid = threadIdx.x;
    const size_t off = row * D_ + tid * 4;

    float4 va = *(const float4*)(a + off);
    float4 vb = *(const float4*)(bres + off);
    float x0 = va.x + vb.x;
    float x1 = va.y + vb.y;
    float x2 = va.z + vb.z;
    float x3 = va.w + vb.w;

    float s  = x0 + x1 + x2 + x3;
    float sq = x0*x0 + x1*x1 + x2*x2 + x3*x3;
#pragma unroll
    for (int o = 16; o; o >>= 1) {
        s  += __shfl_xor_sync(0xffffffffu, s, o);
        sq += __shfl_xor_sync(0xffffffffu, sq, o);
    }
    __shared__ float rs[8];
    __shared__ float rq[8];
    if ((tid & 31) == 0) { rs[tid >> 5] = s; rq[tid >> 5] = sq; }
    __syncthreads();
    s = 0.f; sq = 0.f;
#pragma unroll
    for (int w = 0; w < 8; w++) { s += rs[w]; sq += rq[w]; }

    const float mu  = s * (1.0f / D_);
    const float var = sq * (1.0f / D_) - mu * mu;
    const float inv = rsqrtf(var + 1e-5f);

    float4 g  = *(const float4*)(gamma + tid * 4);
    float4 bt = *(const float4*)(beta + tid * 4);
    float4 o4;
    o4.x = (x0 - mu) * inv * g.x + bt.x;
    o4.y = (x1 - mu) * inv * g.y + bt.y;
    o4.z = (x2 - mu) * inv * g.z + bt.z;
    o4.w = (x3 - mu) * inv * g.w + bt.w;
    *(float4*)(out + off) = o4;
}

// ---------------- launch ----------------------------------------------------
extern "C" void kernel_launch(void* const* d_in, const int* in_sizes, int n_in,
                              void* d_out, int out_size)
{
    const float* x     = (const float*)d_in[0];
    const float* Wq    = (const float*)d_in[1];
    const float* bq    = (const float*)d_in[2];
    const float* Wk    = (const float*)d_in[3];
    const float* bk    = (const float*)d_in[4];
    const float* Wv    = (const float*)d_in[5];
    const float* bv    = (const float*)d_in[6];
    const float* Wo    = (const float*)d_in[7];
    const float* bo    = (const float*)d_in[8];
    const float* W1    = (const float*)d_in[9];
    const float* b1    = (const float*)d_in[10];
    const float* W2    = (const float*)d_in[11];
    const float* b2    = (const float*)d_in[12];
    const float* gamma = (const float*)d_in[13];
    const float* beta  = (const float*)d_in[14];

    float* out  = (float*)d_out;
    float* attn = out + (size_t)B_ * S_ * D_;   // outputs concatenated: out, attn

    float *q, *k, *v, *ao, *t1, *h, *hid;
    cudaGetSymbolAddress((void**)&q,   g_q);
    cudaGetSymbolAddress((void**)&k,   g_k);
    cudaGetSymbolAddress((void**)&v,   g_v);
    cudaGetSymbolAddress((void**)&ao,  g_ao);
    cudaGetSymbolAddress((void**)&t1,  g_t1);
    cudaGetSymbolAddress((void**)&h,   g_h);
    cudaGetSymbolAddress((void**)&hid, g_hid);

    dim3 blk(256);

    // QKV projections
    sgemm_nn<0><<<dim3(D_/128, M_/128), blk>>>(x, Wq, bq, q, M_, D_, D_);
    sgemm_nn<0><<<dim3(D_/128, M_/128), blk>>>(x, Wk, bk, k, M_, D_, D_);
    sgemm_nn<0><<<dim3(D_/128, M_/128), blk>>>(x, Wv, bv, v, M_, D_, D_);

    // attention scores -> softmax (written directly into the attn output)
    energy_kernel<<<dim3(S_/128, S_/128, B_*H_), blk>>>(q, k, attn);
    softmax_kernel<<<B_*H_*S_, blk>>>(attn);

    // attn @ V
    av_kernel<<<dim3(1, S_/128, B_*H_), blk>>>(attn, v, ao);

    // output projection + residual + LN
    sgemm_nn<0><<<dim3(D_/128, M_/128), blk>>>(ao, Wo, bo, t1, M_, D_, D_);
    add_ln_kernel<<<M_, blk>>>(x, t1, gamma, beta, h);

    // MLP
    sgemm_nn<1><<<dim3(HID_/128, M_/128), blk>>>(h, W1, b1, hid, M_, HID_, D_);
    sgemm_nn<0><<<dim3(D_/128, M_/128), blk>>>(hid, W2, b2, t1, M_, D_, HID_);
    add_ln_kernel<<<M_, blk>>>(t1, h, gamma, beta, out);
}

// round 2
// speedup vs baseline: 2.8516x; 2.8516x over previous
#include <cuda_runtime.h>
#include <math.h>
#include <stdint.h>

#define B_   2
#define S_   2048
#define H_   16
#define DH_  64
#define D_   1024
#define HID_ 4096
#define M_   (B_*S_)   // 4096 tokens

// ---------------- scratch (static device globals; no runtime alloc) ----------
__device__ float g_q  [(size_t)M_*D_];
__device__ float g_k  [(size_t)M_*D_];
__device__ float g_v  [(size_t)M_*D_];
__device__ float g_ao [(size_t)M_*D_];
__device__ float g_t1 [(size_t)M_*D_];
__device__ float g_h  [(size_t)M_*D_];
__device__ float g_hid[(size_t)M_*HID_];

// ---------------- helpers ----------------------------------------------------
__device__ __forceinline__ void cp_async16(uint32_t s, const float* g) {
    asm volatile("cp.async.cg.shared.global [%0], [%1], 16;\n" :: "r"(s), "l"(g));
}
__device__ __forceinline__ void cp_commit() {
    asm volatile("cp.async.commit_group;\n");
}
__device__ __forceinline__ uint32_t f2tf32(float f) {
    uint32_t u;
    asm("cvt.rna.tf32.f32 %0, %1;\n" : "=r"(u) : "f"(f));
    return u;
}
__device__ __forceinline__ void mma_tf32(float c[4],
    uint32_t a0, uint32_t a1, uint32_t a2, uint32_t a3,
    uint32_t b0, uint32_t b1)
{
    asm volatile(
        "mma.sync.aligned.m16n8k8.row.col.f32.tf32.tf32.f32 "
        "{%0,%1,%2,%3}, {%4,%5,%6,%7}, {%8,%9}, {%0,%1,%2,%3};\n"
        : "+f"(c[0]), "+f"(c[1]), "+f"(c[2]), "+f"(c[3])
        : "r"(a0), "r"(a1), "r"(a2), "r"(a3), "r"(b0), "r"(b1));
}

// ---------------- tf32 tensor-core GEMM --------------------------------------
// C[M,N] = A[M,K] @ op(B) + bias, optional exact-gelu.
// MODE 0: plain NN (B global is [K,N] row-major).             BN=128
// MODE 1: energy  (batched NT; B global is [N,K] row-major).  BN=128
// MODE 2: AV      (batched NN).                               BN=64
// BM=128, BK=16, 256 threads, 8 warps (2x4), warp tile 64 x (BN/4).
template<int BN, int MODE, int ACT>
__global__ __launch_bounds__(256) void tf32_gemm(
    const float* __restrict__ A, const float* __restrict__ Bm,
    const float* __restrict__ bias, float* __restrict__ C,
    int M, int N, int K, int lda, int ldb, int ldc)
{
    constexpr int  BM = 128, BK = 16;
    constexpr bool NT = (MODE == 1);
    constexpr int  BROWS = NT ? BN : BK;
    constexpr int  BCOLS = NT ? 20 : BN + 4;
    constexpr int  WN = BN / 4;        // warp n extent
    constexpr int  NTILE = WN / 8;     // n8 tiles per warp

    __shared__ float As[2][BM][20];
    __shared__ float Bs[2][BROWS][BCOLS];

    const int tid  = threadIdx.x;
    const int lane = tid & 31;
    const int warp = tid >> 5;
    const int warpRow = (warp & 1) * 64;
    const int warpCol = (warp >> 1) * WN;

    // batch offsets
    size_t aOff = 0, bOff = 0, cOff = 0;
    if (MODE == 1) {
        int z = blockIdx.z;
        size_t hb = (size_t)(z >> 4) * ((size_t)S_ * D_) + (size_t)(z & 15) * DH_;
        aOff = hb; bOff = hb; cOff = (size_t)z * S_ * S_;
    } else if (MODE == 2) {
        int z = blockIdx.z;
        size_t hb = (size_t)(z >> 4) * ((size_t)S_ * D_) + (size_t)(z & 15) * DH_;
        aOff = (size_t)z * S_ * S_; bOff = hb; cOff = hb;
    }
    const float* Ag = A + aOff;
    const float* Bg = Bm + bOff;
    float* Cg = C + cOff;

    const int row0 = blockIdx.y * BM;
    const int col0 = blockIdx.x * BN;

    // loader mappings
    const int ar = tid >> 2;            // 0..63 (rows ar, ar+64)
    const int ac = (tid & 3) << 2;      // 0,4,8,12

    const uint32_t sA = (uint32_t)__cvta_generic_to_shared(&As[0][0][0]);
    const uint32_t sB = (uint32_t)__cvta_generic_to_shared(&Bs[0][0][0]);

    auto issue = [&](int k0, int buf) {
        const float* ap = Ag + (size_t)(row0 + ar) * lda + k0 + ac;
        cp_async16(sA + (uint32_t)(((buf * BM + ar) * 20 + ac) * 4), ap);
        cp_async16(sA + (uint32_t)(((buf * BM + ar + 64) * 20 + ac) * 4),
                   ap + (size_t)64 * lda);
        if (NT) {
            const float* bp = Bg + (size_t)(col0 + ar) * ldb + k0 + ac;
            cp_async16(sB + (uint32_t)(((buf * BROWS + ar) * BCOLS + ac) * 4), bp);
            cp_async16(sB + (uint32_t)(((buf * BROWS + ar + 64) * BCOLS + ac) * 4),
                       bp + (size_t)64 * ldb);
        } else if (BN == 128) {
            const int br = tid >> 5;            // 0..7 (rows br, br+8)
            const int bc = (tid & 31) << 2;     // 0..124
            const float* bp = Bg + (size_t)(k0 + br) * ldb + col0 + bc;
            cp_async16(sB + (uint32_t)(((buf * BROWS + br) * BCOLS + bc) * 4), bp);
            cp_async16(sB + (uint32_t)(((buf * BROWS + br + 8) * BCOLS + bc) * 4),
                       bp + (size_t)8 * ldb);
        } else {  // BN == 64
            const int br = tid >> 4;            // 0..15
            const int bc = (tid & 15) << 2;     // 0..60
            const float* bp = Bg + (size_t)(k0 + br) * ldb + col0 + bc;
            cp_async16(sB + (uint32_t)(((buf * BROWS + br) * BCOLS + bc) * 4), bp);
        }
        cp_commit();
    };

    float acc[4][NTILE][4];
#pragma unroll
    for (int i = 0; i < 4; i++)
#pragma unroll
        for (int j = 0; j < NTILE; j++)
#pragma unroll
            for (int r = 0; r < 4; r++) acc[i][j][r] = 0.f;

    const int NITER = K / BK;
    issue(0, 0);

    for (int it = 0; it < NITER; it++) {
        const int buf = it & 1;
        if (it + 1 < NITER) {
            issue((it + 1) * BK, buf ^ 1);
            asm volatile("cp.async.wait_group 1;\n" ::: "memory");
        } else {
            asm volatile("cp.async.wait_group 0;\n" ::: "memory");
        }
        __syncthreads();

#pragma unroll
        for (int kk = 0; kk < BK; kk += 8) {
            uint32_t af[4][4];
#pragma unroll
            for (int i = 0; i < 4; i++) {
                const int r = warpRow + i * 16 + (lane >> 2);
                const int c = kk + (lane & 3);
                af[i][0] = f2tf32(As[buf][r][c]);
                af[i][1] = f2tf32(As[buf][r + 8][c]);
                af[i][2] = f2tf32(As[buf][r][c + 4]);
                af[i][3] = f2tf32(As[buf][r + 8][c + 4]);
            }
            uint32_t bf[NTILE][2];
#pragma unroll
            for (int j = 0; j < NTILE; j++) {
                const int n = warpCol + j * 8 + (lane >> 2);
                if (NT) {
                    bf[j][0] = f2tf32(Bs[buf][n][kk + (lane & 3)]);
                    bf[j][1] = f2tf32(Bs[buf][n][kk + 4 + (lane & 3)]);
                } else {
                    bf[j][0] = f2tf32(Bs[buf][kk + (lane & 3)][n]);
                    bf[j][1] = f2tf32(Bs[buf][kk + 4 + (lane & 3)][n]);
                }
            }
#pragma unroll
            for (int i = 0; i < 4; i++)
#pragma unroll
                for (int j = 0; j < NTILE; j++)
                    mma_tf32(acc[i][j], af[i][0], af[i][1], af[i][2], af[i][3],
                             bf[j][0], bf[j][1]);
        }
        __syncthreads();
    }

    // epilogue
#pragma unroll
    for (int i = 0; i < 4; i++) {
        const int r = row0 + warpRow + i * 16 + (lane >> 2);
#pragma unroll
        for (int j = 0; j < NTILE; j++) {
            const int c = col0 + warpCol + j * 8 + 2 * (lane & 3);
            float bb0 = 0.f, bb1 = 0.f;
            if (bias) { bb0 = bias[c]; bb1 = bias[c + 1]; }
            float v0 = acc[i][j][0] + bb0;
            float v1 = acc[i][j][1] + bb1;
            float v2 = acc[i][j][2] + bb0;
            float v3 = acc[i][j][3] + bb1;
            if (ACT == 1) {
                v0 = 0.5f * v0 * (1.f + erff(v0 * 0.70710678118654752f));
                v1 = 0.5f * v1 * (1.f + erff(v1 * 0.70710678118654752f));
                v2 = 0.5f * v2 * (1.f + erff(v2 * 0.70710678118654752f));
                v3 = 0.5f * v3 * (1.f + erff(v3 * 0.70710678118654752f));
            }
            *(float2*)(Cg + (size_t)r * ldc + c)       = make_float2(v0, v1);
            *(float2*)(Cg + (size_t)(r + 8) * ldc + c) = make_float2(v2, v3);
        }
    }
}

// ---------------- in-place softmax over rows of length S_, scale 1/8 --------
__global__ __launch_bounds__(256) void softmax_kernel(float* __restrict__ P)
{
    const size_t row = blockIdx.x;
    float* p = P + row * (size_t)S_;
    const int tid = threadIdx.x;

    float v[8];
    float4 v0 = *(const float4*)(p + tid * 8);
    float4 v1 = *(const float4*)(p + tid * 8 + 4);
    v[0] = v0.x; v[1] = v0.y; v[2] = v0.z; v[3] = v0.w;
    v[4] = v1.x; v[5] = v1.y; v[6] = v1.z; v[7] = v1.w;

    float m = v[0];
#pragma unroll
    for (int i = 1; i < 8; i++) m = fmaxf(m, v[i]);
#pragma unroll
    for (int o = 16; o; o >>= 1) m = fmaxf(m, __shfl_xor_sync(0xffffffffu, m, o));

    __shared__ float rmax[8];
    __shared__ float rsum[8];
    if ((tid & 31) == 0) rmax[tid >> 5] = m;
    __syncthreads();
    m = rmax[0];
#pragma unroll
    for (int w = 1; w < 8; w++) m = fmaxf(m, rmax[w]);

    float s = 0.f;
#pragma unroll
    for (int i = 0; i < 8; i++) {
        v[i] = expf((v[i] - m) * 0.125f);
        s += v[i];
    }
#pragma unroll
    for (int o = 16; o; o >>= 1) s += __shfl_xor_sync(0xffffffffu, s, o);
    if ((tid & 31) == 0) rsum[tid >> 5] = s;
    __syncthreads();
    s = 0.f;
#pragma unroll
    for (int w = 0; w < 8; w++) s += rsum[w];
    float inv = 1.0f / s;

    *(float4*)(p + tid * 8)     = make_float4(v[0]*inv, v[1]*inv, v[2]*inv, v[3]*inv);
    *(float4*)(p + tid * 8 + 4) = make_float4(v[4]*inv, v[5]*inv, v[6]*inv, v[7]*inv);
}

// ---------------- fused residual add + LayerNorm over D_ = 1024 -------------
__global__ __launch_bounds__(256) void add_ln_kernel(
    const float* __restrict__ a, const float* __restrict__ bres,
    const float* __restrict__ gamma, const float* __restrict__ beta,
    float* __restrict__ out)
{
    const size_t row = blockIdx.x;
    const int tid = threadIdx.x;
    const size_t off = row * D_ + tid * 4;

    float4 va = *(const float4*)(a + off);
    float4 vb = *(const float4*)(bres + off);
    float x0 = va.x + vb.x;
    float x1 = va.y + vb.y;
    float x2 = va.z + vb.z;
    float x3 = va.w + vb.w;

    float s  = x0 + x1 + x2 + x3;
    float sq = x0*x0 + x1*x1 + x2*x2 + x3*x3;
#pragma unroll
    for (int o = 16; o; o >>= 1) {
        s  += __shfl_xor_sync(0xffffffffu, s, o);
        sq += __shfl_xor_sync(0xffffffffu, sq, o);
    }
    __shared__ float rs[8];
    __shared__ float rq[8];
    if ((tid & 31) == 0) { rs[tid >> 5] = s; rq[tid >> 5] = sq; }
    __syncthreads();
    s = 0.f; sq = 0.f;
#pragma unroll
    for (int w = 0; w < 8; w++) { s += rs[w]; sq += rq[w]; }

    const float mu  = s * (1.0f / D_);
    const float var = sq * (1.0f / D_) - mu * mu;
    const float inv = rsqrtf(var + 1e-5f);

    float4 g  = *(const float4*)(gamma + tid * 4);
    float4 bt = *(const float4*)(beta + tid * 4);
    float4 o4;
    o4.x = (x0 - mu) * inv * g.x + bt.x;
    o4.y = (x1 - mu) * inv * g.y + bt.y;
    o4.z = (x2 - mu) * inv * g.z + bt.z;
    o4.w = (x3 - mu) * inv * g.w + bt.w;
    *(float4*)(out + off) = o4;
}

// ---------------- launch ----------------------------------------------------
extern "C" void kernel_launch(void* const* d_in, const int* in_sizes, int n_in,
                              void* d_out, int out_size)
{
    const float* x     = (const float*)d_in[0];
    const float* Wq    = (const float*)d_in[1];
    const float* bq    = (const float*)d_in[2];
    const float* Wk    = (const float*)d_in[3];
    const float* bk    = (const float*)d_in[4];
    const float* Wv    = (const float*)d_in[5];
    const float* bv    = (const float*)d_in[6];
    const float* Wo    = (const float*)d_in[7];
    const float* bo    = (const float*)d_in[8];
    const float* W1    = (const float*)d_in[9];
    const float* b1    = (const float*)d_in[10];
    const float* W2    = (const float*)d_in[11];
    const float* b2    = (const float*)d_in[12];
    const float* gamma = (const float*)d_in[13];
    const float* beta  = (const float*)d_in[14];

    float* out  = (float*)d_out;
    float* attn = out + (size_t)B_ * S_ * D_;   // outputs concatenated: out, attn

    float *q, *k, *v, *ao, *t1, *h, *hid;
    cudaGetSymbolAddress((void**)&q,   g_q);
    cudaGetSymbolAddress((void**)&k,   g_k);
    cudaGetSymbolAddress((void**)&v,   g_v);
    cudaGetSymbolAddress((void**)&ao,  g_ao);
    cudaGetSymbolAddress((void**)&t1,  g_t1);
    cudaGetSymbolAddress((void**)&h,   g_h);
    cudaGetSymbolAddress((void**)&hid, g_hid);

    dim3 blk(256);

    // QKV projections (tensor core, tf32)
    tf32_gemm<128,0,0><<<dim3(D_/128, M_/128), blk>>>(x, Wq, bq, q, M_, D_, D_, D_, D_, D_);
    tf32_gemm<128,0,0><<<dim3(D_/128, M_/128), blk>>>(x, Wk, bk, k, M_, D_, D_, D_, D_, D_);
    tf32_gemm<128,0,0><<<dim3(D_/128, M_/128), blk>>>(x, Wv, bv, v, M_, D_, D_, D_, D_, D_);

    // attention scores (batched NT) -> softmax (in-place in attn output)
    tf32_gemm<128,1,0><<<dim3(S_/128, S_/128, B_*H_), blk>>>(q, k, nullptr, attn,
                                                             S_, S_, DH_, D_, D_, S_);
    softmax_kernel<<<B_*H_*S_, blk>>>(attn);

    // attn @ V (batched NN, N=64)
    tf32_gemm<64,2,0><<<dim3(1, S_/128, B_*H_), blk>>>(attn, v, nullptr, ao,
                                                       S_, DH_, S_, S_, D_, D_);

    // output projection + residual + LN
    tf32_gemm<128,0,0><<<dim3(D_/128, M_/128), blk>>>(ao, Wo, bo, t1, M_, D_, D_, D_, D_, D_);
    add_ln_kernel<<<M_, blk>>>(x, t1, gamma, beta, h);

    // MLP
    tf32_gemm<128,0,1><<<dim3(HID_/128, M_/128), blk>>>(h, W1, b1, hid, M_, HID_, D_, D_, HID_, HID_);
    tf32_gemm<128,0,0><<<dim3(D_/128, M_/128), blk>>>(hid, W2, b2, t1, M_, D_, HID_, HID_, D_, D_);
    add_ln_kernel<<<M_, blk>>>(t1, h, gamma, beta, out);
}

// round 3
// speedup vs baseline: 2.8689x; 1.0060x over previous
#include <cuda_runtime.h>
#include <math.h>
#include <stdint.h>

#define B_   2
#define S_   2048
#define H_   16
#define DH_  64
#define D_   1024
#define HID_ 4096
#define M_   (B_*S_)   // 4096 tokens
#define NROWS_ (B_*H_*S_)   // 65536 attn rows

// ---------------- scratch (static device globals; no runtime alloc) ----------
__device__ float g_q  [(size_t)M_*D_];
__device__ float g_k  [(size_t)M_*D_];
__device__ float g_v  [(size_t)M_*D_];
__device__ float g_ao [(size_t)M_*D_];
__device__ float g_t1 [(size_t)M_*D_];
__device__ float g_h  [(size_t)M_*D_];
__device__ float g_hid[(size_t)M_*HID_];
__device__ float g_psum[(size_t)NROWS_*16];   // per-row partial exp sums (16 col tiles)
__device__ float g_inv [(size_t)NROWS_];      // per-row 1/sum

// ---------------- helpers ----------------------------------------------------
__device__ __forceinline__ void cp_async16(uint32_t s, const float* g) {
    asm volatile("cp.async.cg.shared.global [%0], [%1], 16;\n" :: "r"(s), "l"(g));
}
__device__ __forceinline__ void cp_commit() {
    asm volatile("cp.async.commit_group;\n");
}
__device__ __forceinline__ uint32_t f2tf32(float f) {
    uint32_t u;
    asm("cvt.rna.tf32.f32 %0, %1;\n" : "=r"(u) : "f"(f));
    return u;
}
__device__ __forceinline__ void mma_tf32(float c[4],
    uint32_t a0, uint32_t a1, uint32_t a2, uint32_t a3,
    uint32_t b0, uint32_t b1)
{
    asm volatile(
        "mma.sync.aligned.m16n8k8.row.col.f32.tf32.tf32.f32 "
        "{%0,%1,%2,%3}, {%4,%5,%6,%7}, {%8,%9}, {%0,%1,%2,%3};\n"
        : "+f"(c[0]), "+f"(c[1]), "+f"(c[2]), "+f"(c[3])
        : "r"(a0), "r"(a1), "r"(a2), "r"(a3), "r"(b0), "r"(b1));
}

// ---------------- tf32 tensor-core GEMM --------------------------------------
// MODE 0: plain NN (B global [K,N] row-major). BN=128. C = A@B + bias (+gelu)
// MODE 1: energy (batched NT, B global [N,K]). BN=128.
//         C = exp((A@B^T)/8); per-row partial sums -> wb (psum layout).
// MODE 2: AV (batched NN). BN=64. C = inv[row] * (A@B); also writes
//         normalized A (=P) back to wb in-place while streaming tiles.
// BM=128, BK=16, 3-stage cp.async, 256 threads, 8 warps, warp tile 64 x BN/4.
template<int BN, int MODE, int ACT>
__global__ __launch_bounds__(256) void tf32_gemm(
    const float* __restrict__ A, const float* __restrict__ Bm,
    const float* __restrict__ bias, const float* __restrict__ extra,
    float* __restrict__ wb, float* __restrict__ C,
    int M, int N, int K, int lda, int ldb, int ldc)
{
    constexpr int  BM = 128, BK = 16;
    constexpr bool NT = (MODE == 1);
    constexpr int  BROWS = NT ? BN : BK;
    constexpr int  BCOLS = NT ? 20 : BN + 4;
    constexpr int  WN = BN / 4;
    constexpr int  NTILE = WN / 8;

    __shared__ float As[3][BM][20];
    __shared__ float Bs[3][BROWS][BCOLS];
    __shared__ float red[(MODE == 1) ? 128 : 1][5];

    const int tid  = threadIdx.x;
    const int lane = tid & 31;
    const int warp = tid >> 5;
    const int warpRow = (warp & 1) * 64;
    const int warpCol = (warp >> 1) * WN;

    // batch offsets
    size_t aOff = 0, bOff = 0, cOff = 0, zrow = 0;
    if (MODE == 1) {
        int z = blockIdx.z;
        size_t hb = (size_t)(z >> 4) * ((size_t)S_ * D_) + (size_t)(z & 15) * DH_;
        aOff = hb; bOff = hb; cOff = (size_t)z * S_ * S_;
        zrow = (size_t)z * S_;
    } else if (MODE == 2) {
        int z = blockIdx.z;
        size_t hb = (size_t)(z >> 4) * ((size_t)S_ * D_) + (size_t)(z & 15) * DH_;
        aOff = (size_t)z * S_ * S_; bOff = hb; cOff = hb;
        zrow = (size_t)z * S_;
    }
    const float* Ag = A + aOff;
    const float* Bg = Bm + bOff;
    float* Cg = C + cOff;

    const int row0 = blockIdx.y * BM;
    const int col0 = blockIdx.x * BN;

    const int ar = tid >> 2;            // 0..63 (rows ar, ar+64)
    const int ac = (tid & 3) << 2;      // 0,4,8,12

    const uint32_t sA = (uint32_t)__cvta_generic_to_shared(&As[0][0][0]);
    const uint32_t sB = (uint32_t)__cvta_generic_to_shared(&Bs[0][0][0]);

    auto issue = [&](int k0, int buf) {
        const float* ap = Ag + (size_t)(row0 + ar) * lda + k0 + ac;
        cp_async16(sA + (uint32_t)(((buf * BM + ar) * 20 + ac) * 4), ap);
        cp_async16(sA + (uint32_t)(((buf * BM + ar + 64) * 20 + ac) * 4),
                   ap + (size_t)64 * lda);
        if (NT) {
            const float* bp = Bg + (size_t)(col0 + ar) * ldb + k0 + ac;
            cp_async16(sB + (uint32_t)(((buf * BROWS + ar) * BCOLS + ac) * 4), bp);
            cp_async16(sB + (uint32_t)(((buf * BROWS + ar + 64) * BCOLS + ac) * 4),
                       bp + (size_t)64 * ldb);
        } else if (BN == 128) {
            const int br = tid >> 5;
            const int bc = (tid & 31) << 2;
            const float* bp = Bg + (size_t)(k0 + br) * ldb + col0 + bc;
            cp_async16(sB + (uint32_t)(((buf * BROWS + br) * BCOLS + bc) * 4), bp);
            cp_async16(sB + (uint32_t)(((buf * BROWS + br + 8) * BCOLS + bc) * 4),
                       bp + (size_t)8 * ldb);
        } else {  // BN == 64
            const int br = tid >> 4;
            const int bc = (tid & 15) << 2;
            const float* bp = Bg + (size_t)(k0 + br) * ldb + col0 + bc;
            cp_async16(sB + (uint32_t)(((buf * BROWS + br) * BCOLS + bc) * 4), bp);
        }
        cp_commit();
    };

    // MODE 2: per-loader-row inverse sums (for normalized write-back of P)
    float invA = 0.f, invB = 0.f;
    float* wbp = nullptr;
    if (MODE == 2) {
        invA = extra[zrow + row0 + ar];
        invB = extra[zrow + row0 + ar + 64];
        wbp = wb + aOff;
    }

    float acc[4][NTILE][4];
#pragma unroll
    for (int i = 0; i < 4; i++)
#pragma unroll
        for (int j = 0; j < NTILE; j++)
#pragma unroll
            for (int r = 0; r < 4; r++) acc[i][j][r] = 0.f;

    const int NITER = K / BK;
    issue(0, 0);
    if (NITER > 1) issue(BK, 1);

    for (int it = 0; it < NITER; it++) {
        const int buf = it % 3;
        if (it < NITER - 1) {
            asm volatile("cp.async.wait_group 1;\n" ::: "memory");
        } else {
            asm volatile("cp.async.wait_group 0;\n" ::: "memory");
        }
        __syncthreads();
        if (it + 2 < NITER) issue((it + 2) * BK, (it + 2) % 3);

        if (MODE == 2) {
            // write normalized P back to the attn output while data is hot
            const int k0 = it * BK;
            float4 pa = *(const float4*)&As[buf][ar][ac];
            float4 pb = *(const float4*)&As[buf][ar + 64][ac];
            float* w0 = wbp + (size_t)(row0 + ar) * lda + k0 + ac;
            float* w1 = wbp + (size_t)(row0 + ar + 64) * lda + k0 + ac;
            *(float4*)w0 = make_float4(pa.x*invA, pa.y*invA, pa.z*invA, pa.w*invA);
            *(float4*)w1 = make_float4(pb.x*invB, pb.y*invB, pb.z*invB, pb.w*invB);
        }

#pragma unroll
        for (int kk = 0; kk < BK; kk += 8) {
            uint32_t af[4][4];
#pragma unroll
            for (int i = 0; i < 4; i++) {
                const int r = warpRow + i * 16 + (lane >> 2);
                const int c = kk + (lane & 3);
                af[i][0] = f2tf32(As[buf][r][c]);
                af[i][1] = f2tf32(As[buf][r + 8][c]);
                af[i][2] = f2tf32(As[buf][r][c + 4]);
                af[i][3] = f2tf32(As[buf][r + 8][c + 4]);
            }
            uint32_t bf[NTILE][2];
#pragma unroll
            for (int j = 0; j < NTILE; j++) {
                const int n = warpCol + j * 8 + (lane >> 2);
                if (NT) {
                    bf[j][0] = f2tf32(Bs[buf][n][kk + (lane & 3)]);
                    bf[j][1] = f2tf32(Bs[buf][n][kk + 4 + (lane & 3)]);
                } else {
                    bf[j][0] = f2tf32(Bs[buf][kk + (lane & 3)][n]);
                    bf[j][1] = f2tf32(Bs[buf][kk + 4 + (lane & 3)][n]);
                }
            }
#pragma unroll
            for (int i = 0; i < 4; i++)
#pragma unroll
                for (int j = 0; j < NTILE; j++)
                    mma_tf32(acc[i][j], af[i][0], af[i][1], af[i][2], af[i][3],
                             bf[j][0], bf[j][1]);
        }
    }

    // ---------------- epilogues ---------------------------------------------
    if (MODE == 1) {
        // exp(acc/8), per-row partial sums (deterministic), store exp values
#pragma unroll
        for (int i = 0; i < 4; i++)
#pragma unroll
            for (int j = 0; j < NTILE; j++)
#pragma unroll
                for (int r = 0; r < 4; r++)
                    acc[i][j][r] = expf(acc[i][j][r] * 0.125f);

        __syncthreads();   // red[] reuse barrier (also after mainloop)
#pragma unroll
        for (int i = 0; i < 4; i++) {
            float sA2 = 0.f, sB2 = 0.f;
#pragma unroll
            for (int j = 0; j < NTILE; j++) {
                sA2 += acc[i][j][0] + acc[i][j][1];
                sB2 += acc[i][j][2] + acc[i][j][3];
            }
            sA2 += __shfl_xor_sync(0xffffffffu, sA2, 1);
            sA2 += __shfl_xor_sync(0xffffffffu, sA2, 2);
            sB2 += __shfl_xor_sync(0xffffffffu, sB2, 1);
            sB2 += __shfl_xor_sync(0xffffffffu, sB2, 2);
            if ((lane & 3) == 0) {
                red[warpRow + i * 16 + (lane >> 2)][warp >> 1] = sA2;
                red[warpRow + i * 16 + (lane >> 2) + 8][warp >> 1] = sB2;
            }
        }
        __syncthreads();
        if (tid < 128) {
            float s = red[tid][0] + red[tid][1] + red[tid][2] + red[tid][3];
            wb[(zrow + row0 + tid) * 16 + blockIdx.x] = s;
        }
    }

#pragma unroll
    for (int i = 0; i < 4; i++) {
        const int r = row0 + warpRow + i * 16 + (lane >> 2);
        float invr = 1.f, invr8 = 1.f;
        if (MODE == 2) {
            invr  = extra[zrow + r];
            invr8 = extra[zrow + r + 8];
        }
#pragma unroll
        for (int j = 0; j < NTILE; j++) {
            const int c = col0 + warpCol + j * 8 + 2 * (lane & 3);
            float bb0 = 0.f, bb1 = 0.f;
            if (MODE == 0 && bias) { bb0 = bias[c]; bb1 = bias[c + 1]; }
            float v0 = acc[i][j][0] + bb0;
            float v1 = acc[i][j][1] + bb1;
            float v2 = acc[i][j][2] + bb0;
            float v3 = acc[i][j][3] + bb1;
            if (MODE == 2) { v0 *= invr; v1 *= invr; v2 *= invr8; v3 *= invr8; }
            if (ACT == 1) {
                v0 = 0.5f * v0 * (1.f + erff(v0 * 0.70710678118654752f));
                v1 = 0.5f * v1 * (1.f + erff(v1 * 0.70710678118654752f));
                v2 = 0.5f * v2 * (1.f + erff(v2 * 0.70710678118654752f));
                v3 = 0.5f * v3 * (1.f + erff(v3 * 0.70710678118654752f));
            }
            *(float2*)(Cg + (size_t)r * ldc + c)       = make_float2(v0, v1);
            *(float2*)(Cg + (size_t)(r + 8) * ldc + c) = make_float2(v2, v3);
        }
    }
}

// ---------------- row-sum inversion ------------------------------------------
__global__ __launch_bounds__(256) void reduce_inv_kernel(
    const float* __restrict__ psum, float* __restrict__ inv)
{
    const int r = blockIdx.x * 256 + threadIdx.x;
    const float* p = psum + (size_t)r * 16;
    float s = 0.f;
#pragma unroll
    for (int i = 0; i < 16; i++) s += p[i];
    inv[r] = 1.0f / s;
}

// ---------------- fused residual add + LayerNorm over D_ = 1024 -------------
__global__ __launch_bounds__(256) void add_ln_kernel(
    const float* __restrict__ a, const float* __restrict__ bres,
    const float* __restrict__ gamma, const float* __restrict__ beta,
    float* __restrict__ out)
{
    const size_t row = blockIdx.x;
    const int tid = threadIdx.x;
    const size_t off = row * D_ + tid * 4;

    float4 va = *(const float4*)(a + off);
    float4 vb = *(const float4*)(bres + off);
    float x0 = va.x + vb.x;
    float x1 = va.y + vb.y;
    float x2 = va.z + vb.z;
    float x3 = va.w + vb.w;

    float s  = x0 + x1 + x2 + x3;
    float sq = x0*x0 + x1*x1 + x2*x2 + x3*x3;
#pragma unroll
    for (int o = 16; o; o >>= 1) {
        s  += __shfl_xor_sync(0xffffffffu, s, o);
        sq += __shfl_xor_sync(0xffffffffu, sq, o);
    }
    __shared__ float rs[8];
    __shared__ float rq[8];
    if ((tid & 31) == 0) { rs[tid >> 5] = s; rq[tid >> 5] = sq; }
    __syncthreads();
    s = 0.f; sq = 0.f;
#pragma unroll
    for (int w = 0; w < 8; w++) { s += rs[w]; sq += rq[w]; }

    const float mu  = s * (1.0f / D_);
    const float var = sq * (1.0f / D_) - mu * mu;
    const float inv = rsqrtf(var + 1e-5f);

    float4 g  = *(const float4*)(gamma + tid * 4);
    float4 bt = *(const float4*)(beta + tid * 4);
    float4 o4;
    o4.x = (x0 - mu) * inv * g.x + bt.x;
    o4.y = (x1 - mu) * inv * g.y + bt.y;
    o4.z = (x2 - mu) * inv * g.z + bt.z;
    o4.w = (x3 - mu) * inv * g.w + bt.w;
    *(float4*)(out + off) = o4;
}

// ---------------- launch ----------------------------------------------------
extern "C" void kernel_launch(void* const* d_in, const int* in_sizes, int n_in,
                              void* d_out, int out_size)
{
    const float* x     = (const float*)d_in[0];
    const float* Wq    = (const float*)d_in[1];
    const float* bq    = (const float*)d_in[2];
    const float* Wk    = (const float*)d_in[3];
    const float* bk    = (const float*)d_in[4];
    const float* Wv    = (const float*)d_in[5];
    const float* bv    = (const float*)d_in[6];
    const float* Wo    = (const float*)d_in[7];
    const float* bo    = (const float*)d_in[8];
    const float* W1    = (const float*)d_in[9];
    const float* b1    = (const float*)d_in[10];
    const float* W2    = (const float*)d_in[11];
    const float* b2    = (const float*)d_in[12];
    const float* gamma = (const float*)d_in[13];
    const float* beta  = (const float*)d_in[14];

    float* out  = (float*)d_out;
    float* attn = out + (size_t)B_ * S_ * D_;

    float *q, *k, *v, *ao, *t1, *h, *hid, *psum, *ginv;
    cudaGetSymbolAddress((void**)&q,    g_q);
    cudaGetSymbolAddress((void**)&k,    g_k);
    cudaGetSymbolAddress((void**)&v,    g_v);
    cudaGetSymbolAddress((void**)&ao,   g_ao);
    cudaGetSymbolAddress((void**)&t1,   g_t1);
    cudaGetSymbolAddress((void**)&h,    g_h);
    cudaGetSymbolAddress((void**)&hid,  g_hid);
    cudaGetSymbolAddress((void**)&psum, g_psum);
    cudaGetSymbolAddress((void**)&ginv, g_inv);

    dim3 blk(256);

    // QKV projections
    tf32_gemm<128,0,0><<<dim3(D_/128, M_/128), blk>>>(x, Wq, bq, nullptr, nullptr, q, M_, D_, D_, D_, D_, D_);
    tf32_gemm<128,0,0><<<dim3(D_/128, M_/128), blk>>>(x, Wk, bk, nullptr, nullptr, k, M_, D_, D_, D_, D_, D_);
    tf32_gemm<128,0,0><<<dim3(D_/128, M_/128), blk>>>(x, Wv, bv, nullptr, nullptr, v, M_, D_, D_, D_, D_, D_);

    // energy -> exp(e/8) written into attn (unnormalized) + row partial sums
    tf32_gemm<128,1,0><<<dim3(S_/128, S_/128, B_*H_), blk>>>(q, k, nullptr, nullptr, psum, attn,
                                                             S_, S_, DH_, D_, D_, S_);
    reduce_inv_kernel<<<NROWS_/256, blk>>>(psum, ginv);

    // AV: O = inv * (P' @ V); normalizes attn in-place while streaming
    tf32_gemm<64,2,0><<<dim3(1, S_/128, B_*H_), blk>>>(attn, v, nullptr, ginv, attn, ao,
                                                       S_, DH_, S_, S_, D_, D_);

    // output projection + residual + LN
    tf32_gemm<128,0,0><<<dim3(D_/128, M_/128), blk>>>(ao, Wo, bo, nullptr, nullptr, t1, M_, D_, D_, D_, D_, D_);
    add_ln_kernel<<<M_, blk>>>(x, t1, gamma, beta, h);

    // MLP
    tf32_gemm<128,0,1><<<dim3(HID_/128, M_/128), blk>>>(h, W1, b1, nullptr, nullptr, hid, M_, HID_, D_, D_, HID_, HID_);
    tf32_gemm<128,0,0><<<dim3(D_/128, M_/128), blk>>>(hid, W2, b2, nullptr, nullptr, t1, M_, D_, HID_, HID_, D_, D_);
    add_ln_kernel<<<M_, blk>>>(t1, h, gamma, beta, out);
}